// round 2
// baseline (speedup 1.0000x reference)
#include <cuda_runtime.h>

// Problem constants
#define Gg      180
#define NATOMS  64
#define NRAD    8
#define NANG    16          // 1+3+5+7 real SH for l=0..3
#define NACC    (NRAD*NANG) // 128
#define RMAXI   13
#define BDIM    27
#define NSPLIT  4
#define NTHREADS 128

// A = 36/180 computed in double then truncated to float, matching jnp.float32(L/G)
#define A_F   (0.2f)
#define RO_F  (2.5f)
// VCELL computed in double precision then cast, matching reference
#define VCELL_F ((float)((36.0/180.0)*(36.0/180.0)*(36.0/180.0)))

// scratch: per (atom, split) partial raw sums [m][lm]
__device__ float g_raw[NATOMS * NSPLIT * NACC];

__global__ __launch_bounds__(NTHREADS, 2)
void proj_kernel(const float* __restrict__ rho, const float* __restrict__ pos)
{
    const int atom  = blockIdx.y;
    const int split = blockIdx.x;
    const int tid   = threadIdx.x;

    __shared__ float spos[3];
    __shared__ int   sIdx[3][BDIM];   // wrapped grid indices per dim
    __shared__ float sOfs[3][BDIM];   // physical offsets per dim (off*a - dr)

    if (tid < 3) spos[tid] = pos[atom * 3 + tid];
    __syncthreads();

    if (tid < 3 * BDIM) {
        int dim = tid / BDIM;
        int o   = tid - dim * BDIM;      // 0..26
        int off = o - RMAXI;             // -13..13
        float p  = spos[dim];
        float cm = rintf(p / A_F);       // round-half-even, same as jnp.round
        float dr = p - __fmul_rn(A_F, cm);
        int ci = (int)cm + off;
        if (ci < 0)    ci += Gg;
        if (ci >= Gg)  ci -= Gg;
        sIdx[dim][o] = ci;
        sOfs[dim][o] = __fadd_rn(__fmul_rn((float)off, A_F), -dr);
    }
    __syncthreads();

    // per-thread accumulators raw[m][lm]
    float acc[NACC];
    #pragma unroll
    for (int q = 0; q < NACC; q++) acc[q] = 0.0f;

    const int i0 = (split * BDIM) / NSPLIT;
    const int i1 = ((split + 1) * BDIM) / NSPLIT;
    const int ncell = (i1 - i0) * BDIM * BDIM;

    const float ro2 = RO_F * RO_F;

    for (int c = tid; c < ncell; c += NTHREADS) {
        int i  = c / (BDIM * BDIM);
        int r  = c - i * (BDIM * BDIM);
        int j  = r / BDIM;
        int k  = r - j * BDIM;
        i += i0;

        float x = sOfs[0][i];
        float y = sOfs[1][j];
        float z = sOfs[2][k];
        float r2 = x * x + y * y + z * z;

        if (r2 < ro2) {
            float rv = __ldg(&rho[(sIdx[0][i] * Gg + sIdx[1][j]) * Gg + sIdx[2][k]]);

            float rinv = rsqrtf(fmaxf(r2, 1e-24f));
            float R  = r2 * rinv;
            float ux = x * rinv, uy = y * rinv, uz = z * rinv;

            // real spherical harmonics l=0..3 (algebraic form)
            float Y[NANG];
            float ux2 = ux * ux, uy2 = uy * uy, uz2 = uz * uz;
            Y[0]  = 0.28209479177387814f;
            Y[1]  = 0.4886025119029199f * uy;
            Y[2]  = 0.4886025119029199f * uz;
            Y[3]  = 0.4886025119029199f * ux;
            Y[4]  = 0.5462742152960396f * (2.0f * ux * uy);
            Y[5]  = 1.0925484305920792f * (uy * uz);
            Y[6]  = 0.31539156525252005f * (3.0f * uz2 - 1.0f);
            Y[7]  = 1.0925484305920792f * (ux * uz);
            Y[8]  = 0.5462742152960396f * (ux2 - uy2);
            Y[9]  = 0.5900435899266435f * uy * (3.0f * ux2 - uy2);
            Y[10] = 1.445305721320277f  * (2.0f * ux * uy * uz);
            Y[11] = 0.4570457994644658f * uy * (5.0f * uz2 - 1.0f);
            Y[12] = 0.3731763325901154f * uz * (5.0f * uz2 - 3.0f);
            Y[13] = 0.4570457994644658f * ux * (5.0f * uz2 - 1.0f);
            Y[14] = 1.445305721320277f  * (ux2 - uy2) * uz;
            Y[15] = 0.5900435899266435f * ux * (ux2 - 3.0f * uy2);

            // phi_m(R) = R^2 * (RO - R)^(m+2), folded with rho
            float b = RO_F - R;
            float t = r2 * (b * b) * rv;   // phi_0 * rho
            #pragma unroll
            for (int m = 0; m < NRAD; m++) {
                #pragma unroll
                for (int lm = 0; lm < NANG; lm++)
                    acc[m * NANG + lm] = fmaf(t, Y[lm], acc[m * NANG + lm]);
                t *= b;
            }
        }
    }

    // block reduction: warp shfl tree, then cross-warp via shared
    __shared__ float sred[NTHREADS / 32][NACC];
    const int warp = tid >> 5;
    const int lane = tid & 31;
    #pragma unroll
    for (int q = 0; q < NACC; q++) {
        float v = acc[q];
        v += __shfl_xor_sync(0xFFFFFFFFu, v, 16);
        v += __shfl_xor_sync(0xFFFFFFFFu, v, 8);
        v += __shfl_xor_sync(0xFFFFFFFFu, v, 4);
        v += __shfl_xor_sync(0xFFFFFFFFu, v, 2);
        v += __shfl_xor_sync(0xFFFFFFFFu, v, 1);
        if (lane == 0) sred[warp][q] = v;
    }
    __syncthreads();

    if (tid < NACC) {
        float v = sred[0][tid] + sred[1][tid] + sred[2][tid] + sred[3][tid];
        g_raw[(atom * NSPLIT + split) * NACC + tid] = v;
    }
}

__global__ void finalize_kernel(const float* __restrict__ W, float* __restrict__ out)
{
    const int atom = blockIdx.x;
    const int q    = threadIdx.x;          // 0..127 = n*16 + lm
    const int n    = q >> 4;
    const int lm   = q & 15;

    float s = 0.0f;
    #pragma unroll
    for (int m = 0; m < NRAD; m++) {
        float rm = 0.0f;
        #pragma unroll
        for (int sp = 0; sp < NSPLIT; sp++)
            rm += g_raw[(atom * NSPLIT + sp) * NACC + m * NANG + lm];
        s = fmaf(W[n * NRAD + m], rm, s);
    }
    out[atom * NACC + q] = s * VCELL_F;
}

extern "C" void kernel_launch(void* const* d_in, const int* in_sizes, int n_in,
                              void* d_out, int out_size)
{
    const float* rho = (const float*)d_in[0];   // [180,180,180]
    const float* pos = (const float*)d_in[1];   // [64,3]
    const float* W   = (const float*)d_in[2];   // [8,8]
    float* out = (float*)d_out;                 // [64,128]

    dim3 grid(NSPLIT, NATOMS);
    proj_kernel<<<grid, NTHREADS>>>(rho, pos);
    finalize_kernel<<<NATOMS, NACC>>>(W, out);
}

// round 3
// speedup vs baseline: 1.0089x; 1.0089x over previous
#include <cuda_runtime.h>

// ---- problem constants ----
#define Gg      180
#define NATOMS  64
#define NRAD    8
#define NANG    16
#define NACC    128           // NRAD*NANG
#define NPAIR   64            // NACC/2 packed f32x2 accumulators
#define RMAXI   13
#define BDIM    27
#define NCELLS  (BDIM*BDIM*BDIM)   // 19683
#define NSPLIT  4
#define NTHREADS 128
#define CAPW    768           // per-warp compacted-list capacity

#define A_F   (0.2f)
#define RO_F  (2.5f)
#define VCELL_F ((float)((36.0/180.0)*(36.0/180.0)*(36.0/180.0)))

// scratch (static __device__: no allocation)
__device__ float g_part[NATOMS * NSPLIT * 4 * NACC];   // per (atom,split,warpseg) partials
__device__ int   g_cnt[NATOMS];                        // arrival counters (self-resetting)

// ---- packed f32x2 helpers (sm_103a) ----
__device__ __forceinline__ unsigned long long pack2(float a, float b) {
    unsigned long long r;
    asm("mov.b64 %0, {%1, %2};" : "=l"(r) : "f"(a), "f"(b));
    return r;
}
__device__ __forceinline__ void ffma2(unsigned long long& acc, unsigned long long a, unsigned long long b) {
    asm("fma.rn.f32x2 %0, %1, %2, %0;" : "+l"(acc) : "l"(a), "l"(b));
}
__device__ __forceinline__ unsigned long long mul2(unsigned long long a, unsigned long long b) {
    unsigned long long r;
    asm("mul.rn.f32x2 %0, %1, %2;" : "=l"(r) : "l"(a), "l"(b));
    return r;
}
__device__ __forceinline__ void unpack2(unsigned long long v, float& a, float& b) {
    asm("mov.b64 {%0, %1}, %2;" : "=f"(a), "=f"(b) : "l"(v));
}

__global__ __launch_bounds__(NTHREADS, 2)
void proj_kernel(const float* __restrict__ rho, const float* __restrict__ pos,
                 const float* __restrict__ W, float* __restrict__ out)
{
    const int atom  = blockIdx.y;
    const int split = blockIdx.x;
    const int tid   = threadIdx.x;
    const int warp  = tid >> 5;
    const int lane  = tid & 31;

    __shared__ float spos[3];
    __shared__ int   sIdx[3][BDIM];
    __shared__ float sOfs[3][BDIM];
    __shared__ unsigned short slist[4 * CAPW];
    __shared__ int   scnt[4];
    __shared__ int   s_old;
    __shared__ float sred[NTHREADS][34];   // chunked transpose for reduction

    if (tid < 3) spos[tid] = pos[atom * 3 + tid];
    __syncthreads();

    if (tid < 3 * BDIM) {
        int dim = tid / BDIM;
        int o   = tid - dim * BDIM;
        int off = o - RMAXI;
        float p  = spos[dim];
        float cm = rintf(p / A_F);                 // round-half-even == jnp.round
        float dr = p - __fmul_rn(A_F, cm);
        int ci = (int)cm + off;
        if (ci < 0)   ci += Gg;
        if (ci >= Gg) ci -= Gg;
        sIdx[dim][o] = ci;
        sOfs[dim][o] = __fadd_rn(__fmul_rn((float)off, A_F), -dr);
    }
    __syncthreads();

    // ---------- phase 1: per-warp deterministic compaction of inside cells ----------
    const float ro2 = RO_F * RO_F;
    int wbase = 0;
    const int NITER = (NCELLS + NTHREADS * NSPLIT - 1) / (NTHREADS * NSPLIT);  // 39
    #pragma unroll 1
    for (int it = 0; it < NITER; ++it) {
        unsigned c = (unsigned)(it * (NTHREADS * NSPLIT) + split * NTHREADS + tid);
        bool valid = c < NCELLS;
        unsigned cc = valid ? c : 0u;
        unsigned i = cc / 729u;
        unsigned r = cc - i * 729u;
        unsigned j = r / 27u;
        unsigned k = r - j * 27u;
        float x = sOfs[0][i], y = sOfs[1][j], z = sOfs[2][k];
        float r2 = x * x + y * y + z * z;
        bool pred = valid && (r2 < ro2);
        unsigned mask = __ballot_sync(0xFFFFFFFFu, pred);
        if (pred) {
            int p = wbase + __popc(mask & ((1u << lane) - 1u));
            if (p < CAPW)
                slist[warp * CAPW + p] = (unsigned short)((i << 10) | (j << 5) | k);
        }
        wbase += __popc(mask);
    }
    if (lane == 0) scnt[warp] = (wbase < CAPW) ? wbase : CAPW;
    __syncthreads();

    // ---------- phase 2: dense accumulation with packed FFMA2 ----------
    unsigned long long acc2[NPAIR];
    #pragma unroll
    for (int q = 0; q < NPAIR; ++q) acc2[q] = 0ull;

    #pragma unroll 1
    for (int seg = 0; seg < 4; ++seg) {
        const int cnt = scnt[seg];
        const unsigned short* lst = &slist[seg * CAPW];
        int idx = tid;
        if (idx >= cnt) continue;

        unsigned cell = lst[idx];
        {
            int i = cell >> 10, j = (cell >> 5) & 31, k = cell & 31;
            // prefetch handled below; first load here
        }
        int i0 = cell >> 10, j0 = (cell >> 5) & 31, k0 = cell & 31;
        float rv = __ldg(&rho[(sIdx[0][i0] * Gg + sIdx[1][j0]) * Gg + sIdx[2][k0]]);

        #pragma unroll 1
        while (true) {
            // prefetch next
            int nidx = idx + NTHREADS;
            bool more = nidx < cnt;
            unsigned ncell = 0; float nrv = 0.0f;
            if (more) {
                ncell = lst[nidx];
                int ni = ncell >> 10, nj = (ncell >> 5) & 31, nk = ncell & 31;
                nrv = __ldg(&rho[(sIdx[0][ni] * Gg + sIdx[1][nj]) * Gg + sIdx[2][nk]]);
            }

            int i = cell >> 10, j = (cell >> 5) & 31, k = cell & 31;
            float x = sOfs[0][i], y = sOfs[1][j], z = sOfs[2][k];
            float r2 = x * x + y * y + z * z;
            float rinv = rsqrtf(fmaxf(r2, 1e-24f));
            rinv = rinv * (1.5f - 0.5f * r2 * rinv * rinv);   // Newton refine
            float R  = r2 * rinv;
            float ux = x * rinv, uy = y * rinv, uz = z * rinv;

            float ux2 = ux * ux, uy2 = uy * uy, uz2 = uz * uz;
            float Y0  = 0.28209479177387814f;
            float Y1  = 0.4886025119029199f * uy;
            float Y2  = 0.4886025119029199f * uz;
            float Y3  = 0.4886025119029199f * ux;
            float Y4  = 0.5462742152960396f * (2.0f * ux * uy);
            float Y5  = 1.0925484305920792f * (uy * uz);
            float Y6  = 0.31539156525252005f * (3.0f * uz2 - 1.0f);
            float Y7  = 1.0925484305920792f * (ux * uz);
            float Y8  = 0.5462742152960396f * (ux2 - uy2);
            float Y9  = 0.5900435899266435f * uy * (3.0f * ux2 - uy2);
            float Y10 = 1.445305721320277f  * (2.0f * ux * uy * uz);
            float Y11 = 0.4570457994644658f * uy * (5.0f * uz2 - 1.0f);
            float Y12 = 0.3731763325901154f * uz * (5.0f * uz2 - 3.0f);
            float Y13 = 0.4570457994644658f * ux * (5.0f * uz2 - 1.0f);
            float Y14 = 1.445305721320277f  * (ux2 - uy2) * uz;
            float Y15 = 0.5900435899266435f * ux * (ux2 - 3.0f * uy2);

            unsigned long long Yp[8];
            Yp[0] = pack2(Y0,  Y1);  Yp[1] = pack2(Y2,  Y3);
            Yp[2] = pack2(Y4,  Y5);  Yp[3] = pack2(Y6,  Y7);
            Yp[4] = pack2(Y8,  Y9);  Yp[5] = pack2(Y10, Y11);
            Yp[6] = pack2(Y12, Y13); Yp[7] = pack2(Y14, Y15);

            float b  = RO_F - R;
            float t0 = r2 * (b * b) * rv;            // phi_0 * rho
            unsigned long long b2 = pack2(b, b);
            unsigned long long t2 = pack2(t0, t0);

            #pragma unroll
            for (int m = 0; m < NRAD; ++m) {
                #pragma unroll
                for (int p = 0; p < 8; ++p)
                    ffma2(acc2[m * 8 + p], t2, Yp[p]);
                if (m < NRAD - 1) t2 = mul2(t2, b2);
            }

            if (!more) break;
            idx = nidx; cell = ncell; rv = nrv;
        }
    }

    // ---------- reduction: 4 chunks of 32 coeffs via shared transpose ----------
    #pragma unroll 1
    for (int ch = 0; ch < 4; ++ch) {
        #pragma unroll
        for (int p = 0; p < 16; ++p) {
            float a, bb; unpack2(acc2[ch * 16 + p], a, bb);
            sred[tid][2 * p]     = a;
            sred[tid][2 * p + 1] = bb;
        }
        __syncthreads();
        int q   = tid & 31;
        int seg = tid >> 5;
        float s = 0.0f;
        #pragma unroll
        for (int t = 0; t < 32; ++t) s += sred[seg * 32 + t][q];
        g_part[(((atom * NSPLIT + split) * 4) + seg) * NACC + ch * 32 + q] = s;
        __syncthreads();
    }

    // ---------- last-block-per-atom finalization (replaces 2nd kernel) ----------
    __threadfence();
    if (tid == 0) s_old = atomicAdd(&g_cnt[atom], 1);
    __syncthreads();
    if (s_old == NSPLIT - 1) {
        __threadfence();
        const int q  = tid;          // 0..127
        const int n  = q >> 4;
        const int lm = q & 15;
        float s = 0.0f;
        #pragma unroll
        for (int m = 0; m < NRAD; ++m) {
            float rm = 0.0f;
            #pragma unroll
            for (int pp = 0; pp < NSPLIT * 4; ++pp)
                rm += g_part[(atom * NSPLIT * 4 + pp) * NACC + m * NANG + lm];
            s = fmaf(W[n * NRAD + m], rm, s);
        }
        out[atom * NACC + q] = s * VCELL_F;
        if (tid == 0) g_cnt[atom] = 0;    // reset for next graph replay
    }
}

extern "C" void kernel_launch(void* const* d_in, const int* in_sizes, int n_in,
                              void* d_out, int out_size)
{
    const float* rho = (const float*)d_in[0];   // [180,180,180]
    const float* pos = (const float*)d_in[1];   // [64,3]
    const float* W   = (const float*)d_in[2];   // [8,8]
    float* out = (float*)d_out;                 // [64,128]

    dim3 grid(NSPLIT, NATOMS);
    proj_kernel<<<grid, NTHREADS>>>(rho, pos, W, out);
}